// round 17
// baseline (speedup 1.0000x reference)
#include <cuda_runtime.h>
#include <cuda_fp16.h>
#include <cstdint>

#define M_TOT 4096
#define N_TOT 11008
#define K_TOT 4096
#define QWC   1376            // N_TOT/8 packed words per k-row
#define NCH   64              // k chunks of 64
#define NTILES (N_TOT / 64)   // 172 n-tiles of 64

#define BM 128
#define BN 128
#define THREADS 128           // 4 warps, 64x64 tiles, no specialization
#define NSTAGE 5

// smem map: A-only stages
#define OFF_BAR 0
#define OFF_STG 1024
#define STG_BYTES 16384
#define OFF_ZS (OFF_STG + NSTAGE * STG_BYTES)   // 82944, half2(zz,sc) 32g x 128n
#define SMEM_TOTAL (OFF_ZS + 16384)             // 99328 -> 2 CTAs/SM

// fp16 bias: 0x6400 = 1024.0, ulp = 1 -> (0x6400|nib) == 1024 + nib exactly
#define BIAS2 0x64006400u

// prepass scratch
__device__ __half   AhG[(size_t)M_TOT * K_TOT];
__device__ unsigned QWPG[(size_t)NTILES * NCH * 512];   // fragment-order packed B

__device__ __forceinline__ uint32_t smem_u32(const void* p) {
    uint32_t a;
    asm("{ .reg .u64 t; cvta.to.shared.u64 t, %1; cvt.u32.u64 %0, t; }"
        : "=r"(a) : "l"(p));
    return a;
}
__device__ __forceinline__ void ldsm4(uint32_t* r, uint32_t addr) {
    asm volatile("ldmatrix.sync.aligned.m8n8.x4.shared.b16 {%0,%1,%2,%3}, [%4];"
                 : "=r"(r[0]), "=r"(r[1]), "=r"(r[2]), "=r"(r[3]) : "r"(addr));
}
__device__ __forceinline__ void mma_f16(float* d, const uint32_t* a, const uint32_t* b) {
    asm volatile(
        "mma.sync.aligned.m16n8k16.row.col.f32.f16.f16.f32 "
        "{%0,%1,%2,%3}, {%4,%5,%6,%7}, {%8,%9}, {%0,%1,%2,%3};"
        : "+f"(d[0]), "+f"(d[1]), "+f"(d[2]), "+f"(d[3])
        : "r"(a[0]), "r"(a[1]), "r"(a[2]), "r"(a[3]), "r"(b[0]), "r"(b[1]));
}
__device__ __forceinline__ void mbar_init(uint32_t m, uint32_t c) {
    asm volatile("mbarrier.init.shared.b64 [%0], %1;" :: "r"(m), "r"(c) : "memory");
}
__device__ __forceinline__ void mbar_arrive(uint32_t m) {
    asm volatile("mbarrier.arrive.shared.b64 _, [%0];" :: "r"(m) : "memory");
}
__device__ __forceinline__ void mbar_wait(uint32_t m, uint32_t parity) {
    uint32_t done;
    asm volatile(
        "{\n\t.reg .pred p;\n\t"
        "mbarrier.try_wait.parity.acquire.cta.shared::cta.b64 p, [%1], %2;\n\t"
        "selp.b32 %0, 1, 0, p;\n\t}"
        : "=r"(done) : "r"(m), "r"(parity) : "memory");
    if (!done) {
        asm volatile(
            "{\n\t.reg .pred P1;\n\t"
            "WL_%=:\n\t"
            "mbarrier.try_wait.parity.acquire.cta.shared::cta.b64 P1, [%0], %1, 0x989680;\n\t"
            "@P1 bra.uni WD_%=;\n\t"
            "bra.uni WL_%=;\n\t"
            "WD_%=:\n\t}"
            :: "r"(m), "r"(parity) : "memory");
    }
}
__device__ __forceinline__ void cp_async16(uint32_t dst, const void* src) {
    asm volatile("cp.async.cg.shared.global [%0], [%1], 16;"
                 :: "r"(dst), "l"(src) : "memory");
}

// ============ prepass 1: A fp32 -> fp16 ============
__global__ void __launch_bounds__(256) cvtA_kernel(const float* __restrict__ A) {
    const size_t base = ((size_t)blockIdx.x * 256 + threadIdx.x) * 8;
    const float4 v0 = *reinterpret_cast<const float4*>(A + base);
    const float4 v1 = *reinterpret_cast<const float4*>(A + base + 4);
    __half2 h0 = __floats2half2_rn(v0.x, v0.y);
    __half2 h1 = __floats2half2_rn(v0.z, v0.w);
    __half2 h2 = __floats2half2_rn(v1.x, v1.y);
    __half2 h3 = __floats2half2_rn(v1.z, v1.w);
    *reinterpret_cast<uint4*>(AhG + base) =
        make_uint4(*(uint32_t*)&h0, *(uint32_t*)&h1, *(uint32_t*)&h2, *(uint32_t*)&h3);
}

// ============ prepass 2: repack QW into fragment order ============
// out word o = (((ntile*64 + chunk)*4 + ks)*32 + lane)*4 + njp holds nibbles
// [q(k0,n0) q(k0+1,n0) q(k0+8,n0) q(k0+9,n0)  q(..,n0+8) x4] with
// n0 = ntile*64 + njp*16 + lane/4, k0 = chunk*64 + ks*16 + (lane%4)*2
__global__ void __launch_bounds__(256) repackB_kernel(const unsigned* __restrict__ QW) {
    const unsigned o = blockIdx.x * 256 + threadIdx.x;
    const int njp = o & 3, lane = (o >> 2) & 31, ks = (o >> 7) & 3;
    const int chunk = (o >> 9) & 63, ntile = o >> 15;
    const int n0 = ntile * 64 + njp * 16 + (lane >> 2);
    const int k0 = chunk * 64 + ks * 16 + (lane & 3) * 2;
    unsigned w = 0;
    #pragma unroll
    for (int j = 0; j < 8; j++) {
        const int n = n0 + ((j >> 2) << 3);
        const int k = k0 + (((j >> 1) & 1) << 3) + (j & 1);
        const unsigned nib = (QW[(size_t)k * QWC + (n >> 3)] >> ((n & 7) * 4)) & 15u;
        w |= nib << (4 * j);
    }
    QWPG[o] = w;
}

// ============ fused GEMM: B in registers, A multistage smem ============
__global__ void __launch_bounds__(THREADS, 2) gemm_f16_kernel(
    const unsigned* __restrict__ QZ, const float* __restrict__ SC,
    float* __restrict__ C)
{
    extern __shared__ char smem[];
    const uint32_t sbase = smem_u32(smem);
    const int tid = threadIdx.x, wid = tid >> 5, lane = tid & 31;
    const int bm = blockIdx.y * BM, bn = blockIdx.x * BN;

    if (tid == 0) {
        #pragma unroll
        for (int s = 0; s < NSTAGE; s++) {
            mbar_init(sbase + OFF_BAR + 16 * s, 128);      // full
            mbar_init(sbase + OFF_BAR + 16 * s + 8, 128);  // empty
        }
    }
    // stage (zz = 1024+zp, sc) as half2 per (group, n)
    uint32_t* zsS = (uint32_t*)(smem + OFF_ZS);
    for (int idx = tid; idx < 4096; idx += THREADS) {
        const int g = idx >> 7, n = idx & 127;
        const int gn = bn + n;
        const unsigned zp = (QZ[(size_t)g * QWC + (gn >> 3)] >> ((gn & 7) * 4)) & 15u;
        const __half2 v = __halves2half2(__float2half_rn(1024.f + (float)zp),
                                         __float2half_rn(SC[(size_t)g * N_TOT + gn]));
        zsS[g * 128 + n] = *(const uint32_t*)&v;
    }
    __syncthreads();

    const int wm = (wid & 1) * 64;
    const int wn = (wid >> 1) * 64;
    const int ntile = blockIdx.x * 2 + (wid >> 1);
    const int rsel = ((lane >> 3) & 1) * 8 + (lane & 7);
    const int hi8  = lane >> 4;
    const int l7   = lane & 7;

    int pe[NSTAGE] = {1, 1, 1, 1, 1};
    int cf[NSTAGE] = {0, 0, 0, 0, 0};

    // A-stage fill: wait empty, 8 cp.async, commit (arrive deferred)
    #define FILL_A(chunk)                                                        \
        {                                                                        \
            const int _s = (chunk) % NSTAGE;                                     \
            mbar_wait(sbase + OFF_BAR + 16 * _s + 8, pe[_s]); pe[_s] ^= 1;       \
            const uint32_t _stg = sbase + OFF_STG + _s * STG_BYTES;              \
            const int _k0 = (chunk) * 64;                                        \
            _Pragma("unroll")                                                    \
            for (int r = 0; r < 8; r++) {                                        \
                const int idx = tid + r * 128;                                   \
                const int m = idx >> 3, c = idx & 7;                             \
                cp_async16(_stg + m * 128 + ((c ^ (m & 7)) << 4),                \
                           AhG + (size_t)(bm + m) * K_TOT + _k0 + c * 8);        \
            }                                                                    \
            asm volatile("cp.async.commit_group;" ::: "memory");                 \
        }

    // prologue: fill stages 0..3; hand over 0..2 (3 stays pending)
    FILL_A(0); FILL_A(1); FILL_A(2); FILL_A(3);
    asm volatile("cp.async.wait_group 1;" ::: "memory");
    #pragma unroll
    for (int ps = 0; ps < NSTAGE - 2; ps++)
        mbar_arrive(sbase + OFF_BAR + 16 * ps);

    // B prefetch buffers (fragment-order words)
    const unsigned* qwp = QWPG + (size_t)ntile * NCH * 512 + lane * 4;
    uint4 wbuf[2][4];
    #pragma unroll
    for (int ks = 0; ks < 4; ks++)
        wbuf[0][ks] = *reinterpret_cast<const uint4*>(qwp + 0 * 512 + ks * 128);

    uint32_t zz2[8], sc2[8];
    float accF[4][8][4];
    #pragma unroll
    for (int i = 0; i < 4; i++)
        #pragma unroll
        for (int j = 0; j < 8; j++)
            #pragma unroll
            for (int e = 0; e < 4; e++) accF[i][j][e] = 0.f;

    for (int it = 0; it < NCH; ++it) {
        const int cb = it & 1;
        if (it + 1 < NCH) {
            #pragma unroll
            for (int ks = 0; ks < 4; ks++)
                wbuf[cb ^ 1][ks] = *reinterpret_cast<const uint4*>(
                    qwp + (size_t)(it + 1) * 512 + ks * 128);
        }
        if ((it & 1) == 0) {
            const int g = it >> 1;
            #pragma unroll
            for (int j = 0; j < 8; j++) {
                const uint32_t v = zsS[g * 128 + wn + j * 8 + (lane >> 2)];
                const __half2 h = *(const __half2*)&v;
                const __half2 a = __half2half2(__low2half(h));
                const __half2 b = __half2half2(__high2half(h));
                zz2[j] = *(const uint32_t*)&a;
                sc2[j] = *(const uint32_t*)&b;
            }
        }
        const int s = it % NSTAGE;
        mbar_wait(sbase + OFF_BAR + 16 * s, cf[s]); cf[s] ^= 1;
        const uint32_t aB = sbase + OFF_STG + s * STG_BYTES;

        #pragma unroll
        for (int ks = 0; ks < 4; ks++) {
            const unsigned wq[4] = {wbuf[cb][ks].x, wbuf[cb][ks].y,
                                    wbuf[cb][ks].z, wbuf[cb][ks].w};
            uint32_t bq[8][2];
            #pragma unroll
            for (int njp = 0; njp < 4; njp++) {
                const unsigned w = wq[njp];
                #pragma unroll
                for (int h = 0; h < 4; h++) {
                    const unsigned v = w >> (8 * h);
                    uint32_t u = BIAS2 | (v & 0xFu) | ((v & 0xF0u) << 12);
                    const int nj = njp * 2 + (h >> 1);
                    __half2 q = __hsub2(*(__half2*)&u, *(__half2*)&zz2[nj]);
                    __half2 b = __hmul2(q, *(__half2*)&sc2[nj]);
                    bq[nj][h & 1] = *(uint32_t*)&b;
                }
            }
            #pragma unroll
            for (int mi = 0; mi < 4; mi++) {
                const int m = wm + mi * 16 + rsel;
                uint32_t a[4];
                ldsm4(a, aB + m * 128 + (((ks * 2 + hi8) ^ l7) << 4));
                #pragma unroll
                for (int nj = 0; nj < 8; nj++) mma_f16(accF[mi][nj], a, bq[nj]);
            }
        }
        mbar_arrive(sbase + OFF_BAR + 16 * s + 8);   // empty

        const int c2 = it + NSTAGE - 1;
        if (c2 < NCH) {
            FILL_A(c2);
            asm volatile("cp.async.wait_group 1;" ::: "memory");
            mbar_arrive(sbase + OFF_BAR + 16 * ((c2 - 1) % NSTAGE));
        } else if (c2 == NCH) {
            asm volatile("cp.async.wait_group 0;" ::: "memory");
            mbar_arrive(sbase + OFF_BAR + 16 * ((NCH - 1) % NSTAGE));
        }
    }

    // epilogue
    #pragma unroll
    for (int mi = 0; mi < 4; mi++)
        #pragma unroll
        for (int nj = 0; nj < 8; nj++) {
            const float* a = accF[mi][nj];
            const int row = bm + wm + mi * 16 + (lane >> 2);
            const int col = bn + wn + nj * 8 + (lane & 3) * 2;
            *reinterpret_cast<float2*>(&C[(size_t)row * N_TOT + col]) =
                make_float2(a[0], a[1]);
            *reinterpret_cast<float2*>(&C[(size_t)(row + 8) * N_TOT + col]) =
                make_float2(a[2], a[3]);
        }
}

extern "C" void kernel_launch(void* const* d_in, const int* in_sizes, int n_in,
                              void* d_out, int out_size)
{
    const float*    A  = (const float*)d_in[0];
    const unsigned* QW = (const unsigned*)d_in[1];
    const unsigned* QZ = (const unsigned*)d_in[2];
    const float*    SC = (const float*)d_in[3];
    float*          C  = (float*)d_out;

    cvtA_kernel<<<(M_TOT * K_TOT) / (256 * 8), 256>>>(A);
    repackB_kernel<<<(NTILES * NCH * 512) / 256, 256>>>(QW);

    cudaFuncSetAttribute(gemm_f16_kernel,
                         cudaFuncAttributeMaxDynamicSharedMemorySize, SMEM_TOTAL);
    dim3 grid(N_TOT / BN, M_TOT / BM);   // (86, 32)
    gemm_f16_kernel<<<grid, THREADS, SMEM_TOTAL>>>(QZ, SC, C);
}